// round 15
// baseline (speedup 1.0000x reference)
#include <cuda_runtime.h>
#include <cuda_bf16.h>
#include <cstdint>
#include <math.h>

// Problem constants
#define NB    4
#define NSEQ  16
#define LL    4608
#define CC    256
#define DD    512
#define MM    73728
#define HH    96
#define WW    96
#define HW    9216
#define RNK   16
#define NST   16
#define NCHUNK 16
#define CH    288      // LL / NCHUNK
#define SUB   72       // dbc smem slab rows (CH/SUB = 4)

typedef unsigned long long ull;

// ---------------- scratch (device globals) ----------------
__device__ __align__(16) __nv_bfloat16 g_xg [(size_t)MM * CC];   // gathered x (n,l,c) bf16
__device__ __align__(16) float g_mu[MM];                         // LN mean per row
__device__ __align__(16) float g_rs[MM];                         // LN rstd per row
__device__ __align__(16) float g_u1[1024];                       // W @ nw
__device__ __align__(16) float g_u2[1024];                       // W @ nb
__device__ __align__(16) __nv_bfloat16 g_xi [(size_t)MM * DD];   // in_proj xi half bf16
__device__ __align__(16) __nv_bfloat16 g_z  [(size_t)MM * DD];   // in_proj z half bf16
__device__ __align__(16) __nv_bfloat16 g_xcb[(size_t)MM * DD];   // conv+silu bf16
__device__ __align__(16) float g_dbc[(size_t)MM * 48];           // x_proj out compact: [dt_in|B|C]
__device__ __align__(16) float g_dtf[(size_t)MM * DD];           // dt (fp32), scan1 -> scan2
__device__ __align__(16) __nv_bfloat16 g_ybf[(size_t)MM * DD];   // y bf16
__device__ __align__(16) __nv_bfloat16 g_outTb[(size_t)CC * MM]; // out_proj result, c-major bf16
__device__ __align__(16) __nv_bfloat16 g_wib[1024 * 256];        // (in_proj_w * nw) bf16
__device__ __align__(16) __nv_bfloat16 g_wob[256 * 512];         // out_proj_w bf16
__device__ __align__(16) __nv_bfloat16 g_wxb[64 * 512];          // x_proj_w bf16 padded 48->64
__device__ __align__(16) float g_P [(size_t)NSEQ * NCHUNK * DD * NST];
__device__ __align__(16) float g_he[(size_t)NSEQ * NCHUNK * DD * NST];
__device__ __align__(16) float g_h0[(size_t)NSEQ * NCHUNK * DD * NST];

// ---------------- f32x2 packed math helpers ----------------
__device__ __forceinline__ ull pack2(float lo, float hi) {
    ull r; asm("mov.b64 %0, {%1,%2};" : "=l"(r) : "f"(lo), "f"(hi)); return r;
}
__device__ __forceinline__ void unpack2(ull v, float& lo, float& hi) {
    asm("mov.b64 {%0,%1}, %2;" : "=f"(lo), "=f"(hi) : "l"(v));
}
__device__ __forceinline__ ull fma2(ull a, ull b, ull c) {
    ull d; asm("fma.rn.f32x2 %0, %1, %2, %3;" : "=l"(d) : "l"(a), "l"(b), "l"(c)); return d;
}
__device__ __forceinline__ ull mul2(ull a, ull b) {
    ull d; asm("mul.rn.f32x2 %0, %1, %2;" : "=l"(d) : "l"(a), "l"(b)); return d;
}

// ---------------- K_pt: fused weight prep (blocks 0..1343) + gather-transpose (rest) ----------------
__global__ void k_pt(const float* __restrict__ inw, const float* __restrict__ opw,
                     const float* __restrict__ xpw, const float* __restrict__ nw,
                     const float* __restrict__ nb,
                     const float* __restrict__ d0, const float* __restrict__ d1)
{
    int bid = blockIdx.x;
    int tid = threadIdx.x;
    if (bid < 1024) {
        int e = bid, c = tid;
        float wv = inw[e*256 + c];
        float nwc = nw[c];
        g_wib[e*256 + c] = __float2bfloat16(wv * nwc);
        float s1 = wv * nwc, s2 = wv * nb[c];
        #pragma unroll
        for (int o = 16; o > 0; o >>= 1) {
            s1 += __shfl_xor_sync(0xffffffffu, s1, o);
            s2 += __shfl_xor_sync(0xffffffffu, s2, o);
        }
        __shared__ float a1[8], a2[8];
        int wid = c >> 5;
        if ((c & 31) == 0) { a1[wid] = s1; a2[wid] = s2; }
        __syncthreads();
        if (c == 0) {
            float t1 = 0.f, t2 = 0.f;
            #pragma unroll
            for (int q = 0; q < 8; q++) { t1 += a1[q]; t2 += a2[q]; }
            g_u1[e] = t1; g_u2[e] = t2;
        }
        return;
    } else if (bid < 1280) {
        int r = bid - 1024, c = tid;
        g_wob[r*512 + c]       = __float2bfloat16(opw[r*512 + c]);
        g_wob[r*512 + c + 256] = __float2bfloat16(opw[r*512 + c + 256]);
        return;
    } else if (bid < 1344) {
        int r = bid - 1280, c = tid;
        float v0 = (r < 48) ? xpw[r*512 + c]       : 0.f;
        float v1 = (r < 48) ? xpw[r*512 + c + 256] : 0.f;
        g_wxb[r*512 + c]       = __float2bfloat16(v0);
        g_wxb[r*512 + c + 256] = __float2bfloat16(v1);
        return;
    }

    // gather-transpose part
    __shared__ float tile[32][33];
    int t  = bid - 1344;                 // 0..18431
    int h  = t % 96;
    int rest = t / 96;                   // 0..191
    int wt = (rest % 24) % 3, ct = (rest % 24) / 3;
    int bd = rest / 24;
    int b = bd >> 1, d = bd & 1;
    int w0 = wt * 32, c0 = ct * 32;
    int tx = tid & 31, ty = tid >> 5;

    const float* src = d ? d1 : d0;
    #pragma unroll
    for (int s = 0; s < 4; s++) {
        int cl = ty + s * 8;
        tile[cl][tx] = src[((size_t)(b*CC + c0 + cl)*HH + h)*WW + w0 + tx];
    }
    __syncthreads();

    #pragma unroll
    for (int s = 0; s < 4; s++) {
        int wl = ty + s * 8;
        int w  = w0 + wl;
        float v = tile[tx][wl];
        int k, l;
        if ((h & 1) == 0) {
            if ((w & 1) == 0) { k = 0; l = (h>>1)*96 + (w>>1) + 48*d; }
            else              { k = 2; l = (LL-1) - ((h>>1)*96 + (w>>1) + 48*d); }
        } else {
            if ((w & 1) == 1) { k = 1; l = (w>>1)*96 + (h>>1) + 48*d; }
            else              { k = 3; l = (LL-1) - ((w>>1)*96 + (h>>1) + 48*d); }
        }
        int n = b*4 + k;
        g_xg[((size_t)n*LL + l)*CC + c0 + tx] = __float2bfloat16(v);
    }
}

// ---------------- K_stats: per-row LN stats ----------------
__global__ void k_stats()
{
    int row = blockIdx.x * 8 + (threadIdx.x >> 5);
    int lane = threadIdx.x & 31;
    const __nv_bfloat16* p = &g_xg[(size_t)row * CC];

    uint4 u = *(const uint4*)&p[lane * 8];
    const __nv_bfloat162* h2 = (const __nv_bfloat162*)&u;
    float s1 = 0.f, s2 = 0.f;
    #pragma unroll
    for (int q = 0; q < 4; q++) {
        float2 f = __bfloat1622float2(h2[q]);
        s1 += f.x + f.y;
        s2 += f.x*f.x + f.y*f.y;
    }
    #pragma unroll
    for (int o = 16; o > 0; o >>= 1) {
        s1 += __shfl_xor_sync(0xffffffffu, s1, o);
        s2 += __shfl_xor_sync(0xffffffffu, s2, o);
    }
    if (lane == 0) {
        float mean = s1 * (1.f/256.f);
        float var  = s2 * (1.f/256.f) - mean*mean;
        g_mu[row] = mean;
        g_rs[row] = rsqrtf(var + 1e-5f);
    }
}

// ---------------- mma helpers ----------------
__device__ __forceinline__ unsigned int smem_u32(const void* p) {
    return (unsigned int)__cvta_generic_to_shared(p);
}
__device__ __forceinline__ void ldsm4(unsigned int* r, unsigned int addr) {
    asm volatile("ldmatrix.sync.aligned.m8n8.x4.shared.b16 {%0,%1,%2,%3}, [%4];"
                 : "=r"(r[0]), "=r"(r[1]), "=r"(r[2]), "=r"(r[3]) : "r"(addr));
}
__device__ __forceinline__ void mma16816(float* c, const unsigned int* a,
                                         unsigned int b0, unsigned int b1) {
    asm volatile("mma.sync.aligned.m16n8k16.row.col.f32.bf16.bf16.f32 "
                 "{%0,%1,%2,%3},{%4,%5,%6,%7},{%8,%9},{%0,%1,%2,%3};"
                 : "+f"(c[0]), "+f"(c[1]), "+f"(c[2]), "+f"(c[3])
                 : "r"(a[0]), "r"(a[1]), "r"(a[2]), "r"(a[3]), "r"(b0), "r"(b1));
}
__device__ __forceinline__ void cpa16(unsigned int d, const void* s) {
    asm volatile("cp.async.cg.shared.global [%0], [%1], 16;" :: "r"(d), "l"(s));
}
__device__ __forceinline__ void cp_commit() { asm volatile("cp.async.commit_group;"); }
template<int N> __device__ __forceinline__ void cp_wait() {
    asm volatile("cp.async.wait_group %0;" :: "n"(N));
}

// ---------------- hgemm 128x128x32, 2-stage cp.async (proven) ----------------
template<int MODE>
__global__ __launch_bounds__(256) void hgemm128(
    const __nv_bfloat16* __restrict__ A, const __nv_bfloat16* __restrict__ B,
    __nv_bfloat16* __restrict__ O1, __nv_bfloat16* __restrict__ O2,
    int Kd)
{
    const int LDS = 40;
    __shared__ __nv_bfloat16 As[2][128 * LDS];
    __shared__ __nv_bfloat16 Bs[2][128 * LDS];

    int tid  = threadIdx.x;
    int wid  = tid >> 5, lane = tid & 31;
    int wm   = (wid & 1) * 64;
    int wn   = (wid >> 1) * 32;
    int m0   = blockIdx.y * 128;
    int n0   = blockIdx.x * 128;

    float c[4][4][4];
    #pragma unroll
    for (int i = 0; i < 4; i++)
        #pragma unroll
        for (int j = 0; j < 4; j++)
            #pragma unroll
            for (int q = 0; q < 4; q++) c[i][j][q] = 0.f;

    int ar = tid >> 2;
    int ac = (tid & 3) * 8;
    int NK = Kd >> 5;

    {
        cpa16(smem_u32(&As[0][ar*LDS + ac]),        &A[(size_t)(m0 + ar)      * Kd + ac]);
        cpa16(smem_u32(&As[0][(ar+64)*LDS + ac]),   &A[(size_t)(m0 + ar + 64) * Kd + ac]);
        cpa16(smem_u32(&Bs[0][ar*LDS + ac]),        &B[(size_t)(n0 + ar)      * Kd + ac]);
        cpa16(smem_u32(&Bs[0][(ar+64)*LDS + ac]),   &B[(size_t)(n0 + ar + 64) * Kd + ac]);
        cp_commit();
    }

    for (int it = 0; it < NK; it++) {
        if (it + 1 < NK) {
            int st = (it + 1) & 1, k0 = (it + 1) * 32;
            cpa16(smem_u32(&As[st][ar*LDS + ac]),      &A[(size_t)(m0 + ar)      * Kd + k0 + ac]);
            cpa16(smem_u32(&As[st][(ar+64)*LDS + ac]), &A[(size_t)(m0 + ar + 64) * Kd + k0 + ac]);
            cpa16(smem_u32(&Bs[st][ar*LDS + ac]),      &B[(size_t)(n0 + ar)      * Kd + k0 + ac]);
            cpa16(smem_u32(&Bs[st][(ar+64)*LDS + ac]), &B[(size_t)(n0 + ar + 64) * Kd + k0 + ac]);
            cp_commit();
            cp_wait<1>();
        } else {
            cp_wait<0>();
        }
        __syncthreads();

        int cur = it & 1;
        #pragma unroll
        for (int ks = 0; ks < 2; ks++) {
            int kk = ks * 16;
            unsigned int a[4][4], b[2][4];
            #pragma unroll
            for (int i = 0; i < 4; i++)
                ldsm4(a[i], smem_u32(&As[cur][(wm + i*16 + (lane & 15)) * LDS + kk + ((lane >> 4) * 8)]));
            #pragma unroll
            for (int j2 = 0; j2 < 2; j2++)
                ldsm4(b[j2], smem_u32(&Bs[cur][(wn + j2*16 + (lane & 15)) * LDS + kk + ((lane >> 4) * 8)]));
            #pragma unroll
            for (int i = 0; i < 4; i++)
                #pragma unroll
                for (int j2 = 0; j2 < 2; j2++) {
                    mma16816(c[i][2*j2+0], a[i], b[j2][0], b[j2][2]);
                    mma16816(c[i][2*j2+1], a[i], b[j2][1], b[j2][3]);
                }
        }
        __syncthreads();
    }

    int g = lane >> 2, t4 = lane & 3;
    #pragma unroll
    for (int i = 0; i < 4; i++) {
        int r0 = m0 + wm + i*16 + g;
        int r1 = r0 + 8;
        float f0 = 0.f, g0 = 0.f, f1 = 0.f, g1 = 0.f;
        if (MODE == 1) {
            f0 = g_rs[r0]; g0 = -f0 * g_mu[r0];
            f1 = g_rs[r1]; g1 = -f1 * g_mu[r1];
        }
        #pragma unroll
        for (int j = 0; j < 4; j++) {
            int col = n0 + wn + j*8 + t4*2;
            if (MODE == 1) {
                float U10 = g_u1[col], U11 = g_u1[col+1];
                float U20 = g_u2[col], U21 = g_u2[col+1];
                float v00 = c[i][j][0]*f0 + g0*U10 + U20;
                float v01 = c[i][j][1]*f0 + g0*U11 + U21;
                float v10 = c[i][j][2]*f1 + g1*U10 + U20;
                float v11 = c[i][j][3]*f1 + g1*U11 + U21;
                __nv_bfloat162 a01 = __floats2bfloat162_rn(v00, v01);
                __nv_bfloat162 a23 = __floats2bfloat162_rn(v10, v11);
                if (col < 512) {
                    *(__nv_bfloat162*)&O1[(size_t)r0 * 512 + col] = a01;
                    *(__nv_bfloat162*)&O1[(size_t)r1 * 512 + col] = a23;
                } else {
                    *(__nv_bfloat162*)&O2[(size_t)r0 * 512 + col - 512] = a01;
                    *(__nv_bfloat162*)&O2[(size_t)r1 * 512 + col - 512] = a23;
                }
            } else {
                O1[(size_t)col * MM + r0]     = __float2bfloat16(c[i][j][0]);
                O1[(size_t)(col+1) * MM + r0] = __float2bfloat16(c[i][j][1]);
                O1[(size_t)col * MM + r1]     = __float2bfloat16(c[i][j][2]);
                O1[(size_t)(col+1) * MM + r1] = __float2bfloat16(c[i][j][3]);
            }
        }
    }
}

// ---------------- x_proj GEMM with fused conv+silu A-build (proven) ----------------
__global__ __launch_bounds__(256) void k_xproj(const float* __restrict__ cw, const float* __restrict__ cb)
{
    const int LDS = 40;
    __shared__ __nv_bfloat16 As[128 * LDS];
    __shared__ __nv_bfloat16 Bs[64 * LDS];
    __shared__ float scw[512*4];
    __shared__ float scb[512];

    int tid = threadIdx.x;
    int wid = tid >> 5, lane = tid & 31;
    int wm  = (wid & 3) * 32;
    int wn  = (wid >> 2) * 32;
    int m0  = blockIdx.x * 128;

    for (int i = tid; i < 2048; i += 256) scw[i] = cw[i];
    for (int i = tid; i < 512;  i += 256) scb[i] = cb[i];

    float c[2][4][4];
    #pragma unroll
    for (int i = 0; i < 2; i++)
        #pragma unroll
        for (int j = 0; j < 4; j++)
            #pragma unroll
            for (int q = 0; q < 4; q++) c[i][j][q] = 0.f;

    int R  = tid >> 2;
    int k8 = (tid & 3) * 8;
    int lr1 = (m0 + R) % LL;
    int lr2 = (m0 + R + 64) % LL;
    __syncthreads();

    for (int k0 = 0; k0 < 512; k0 += 32) {
        #pragma unroll
        for (int pass = 0; pass < 2; pass++) {
            int r  = R + pass*64;
            int m  = m0 + r;
            int lr = pass ? lr2 : lr1;
            float acc[8];
            #pragma unroll
            for (int q = 0; q < 8; q++) acc[q] = scb[k0 + k8 + q];
            #pragma unroll
            for (int t = 0; t < 4; t++) {
                if (lr - 3 + t >= 0) {
                    uint4 u = *(const uint4*)&g_xi[(size_t)(m - 3 + t)*512 + k0 + k8];
                    __nv_bfloat162* p = (__nv_bfloat162*)&u;
                    #pragma unroll
                    for (int q2 = 0; q2 < 4; q2++) {
                        float2 f = __bfloat1622float2(p[q2]);
                        acc[2*q2+0] = fmaf(f.x, scw[(k0+k8+2*q2+0)*4 + t], acc[2*q2+0]);
                        acc[2*q2+1] = fmaf(f.y, scw[(k0+k8+2*q2+1)*4 + t], acc[2*q2+1]);
                    }
                }
            }
            uint4 o;
            __nv_bfloat162* q = (__nv_bfloat162*)&o;
            #pragma unroll
            for (int q2 = 0; q2 < 4; q2++) {
                float v0 = acc[2*q2+0], v1 = acc[2*q2+1];
                v0 = v0 / (1.f + __expf(-v0));
                v1 = v1 / (1.f + __expf(-v1));
                q[q2] = __floats2bfloat162_rn(v0, v1);
            }
            *(uint4*)&As[r * LDS + k8] = o;
            *(uint4*)&g_xcb[(size_t)m * 512 + k0 + k8] = o;
        }
        *(uint4*)&Bs[R * LDS + k8] = *(const uint4*)&g_wxb[(size_t)R * 512 + k0 + k8];
        __syncthreads();

        #pragma unroll
        for (int ks = 0; ks < 2; ks++) {
            int kk = ks * 16;
            unsigned int a[2][4], b[2][4];
            #pragma unroll
            for (int i = 0; i < 2; i++)
                ldsm4(a[i], smem_u32(&As[(wm + i*16 + (lane & 15)) * LDS + kk + ((lane >> 4) * 8)]));
            #pragma unroll
            for (int j2 = 0; j2 < 2; j2++)
                ldsm4(b[j2], smem_u32(&Bs[(wn + j2*16 + (lane & 15)) * LDS + kk + ((lane >> 4) * 8)]));
            #pragma unroll
            for (int i = 0; i < 2; i++)
                #pragma unroll
                for (int j2 = 0; j2 < 2; j2++) {
                    mma16816(c[i][2*j2+0], a[i], b[j2][0], b[j2][2]);
                    mma16816(c[i][2*j2+1], a[i], b[j2][1], b[j2][3]);
                }
        }
        __syncthreads();
    }

    int g = lane >> 2, t4 = lane & 3;
    #pragma unroll
    for (int i = 0; i < 2; i++)
        #pragma unroll
        for (int j = 0; j < 4; j++) {
            int row = m0 + wm + i*16 + g;
            int col = wn + j*8 + t4*2;
            if (col < 48) {
                *(float2*)&g_dbc[(size_t)row * 48 + col]       = make_float2(c[i][j][0], c[i][j][1]);
                *(float2*)&g_dbc[(size_t)(row + 8) * 48 + col] = make_float2(c[i][j][2], c[i][j][3]);
            }
        }
}

// ---------------- packed dt: dv·dtw + b -> softplus ----------------
__device__ __forceinline__ float dt_packed(const ull* dv2, const ull* dtw2, float dtbv)
{
    ull acc = pack2(dtbv, 0.f);
    #pragma unroll
    for (int r = 0; r < 8; r++) acc = fma2(dv2[r], dtw2[r], acc);
    float lo, hi; unpack2(acc, lo, hi);
    float v = lo + hi;
    return (v > 15.f) ? v : __logf(1.f + __expf(v));
}

// ---------------- scan pass 1: computes + STORES dt ----------------
__global__ void k_scan1(const float* __restrict__ Alog,
                        const float* __restrict__ dtw, const float* __restrict__ dtb)
{
    __shared__ float sdbc[SUB * 32];   // cols 0..31: [dt_in | B]
    int n  = blockIdx.z;
    int ch = blockIdx.y;
    int e  = blockIdx.x * 128 + threadIdx.x;

    float a[NST];
    #pragma unroll
    for (int s = 0; s < NST; s++) a[s] = -__expf(Alog[e*NST + s]);
    float a0 = a[0];
    bool fast = (a0 < 0.f);
    #pragma unroll
    for (int s = 0; s < NST; s++)
        fast = fast && (fabsf(a[s]/a0 - (float)(s+1)) < 1e-3f);

    ull dtw2[8];
    #pragma unroll
    for (int r = 0; r < 8; r++) dtw2[r] = pack2(dtw[e*RNK + 2*r], dtw[e*RNK + 2*r + 1]);
    float dtbv = dtb[e];

    ull h2[8];
    #pragma unroll
    for (int k = 0; k < 8; k++) h2[k] = pack2(0.f, 0.f);
    float sdt = 0.f;
    int l0 = ch * CH;

    for (int sl = 0; sl < CH; sl += SUB) {
        __syncthreads();
        const float* gsrc = &g_dbc[((size_t)n*LL + l0 + sl) * 48];
        for (int idx = threadIdx.x; idx < SUB*32; idx += 128) {
            int r = idx >> 5, cI = idx & 31;
            sdbc[idx] = gsrc[r*48 + cI];
        }
        __syncthreads();

        for (int r = 0; r < SUB; r++) {
            size_t row = (size_t)n*LL + l0 + sl + r;
            const float* dr = &sdbc[r * 32];
            ull dv2[8], bb2[8];
            #pragma unroll
            for (int q = 0; q < 4; q++) {
                float4 t0 = ((const float4*)dr)[q];
                dv2[2*q+0] = pack2(t0.x, t0.y); dv2[2*q+1] = pack2(t0.z, t0.w);
                float4 t1 = ((const float4*)dr)[4+q];
                bb2[2*q+0] = pack2(t1.x, t1.y); bb2[2*q+1] = pack2(t1.z, t1.w);
            }
            float dtv = dt_packed(dv2, dtw2, dtbv);
            g_dtf[row*DD + e] = dtv;          // hand off to scan2
            float xcv = __bfloat162float(g_xcb[row*DD + e]);
            float w = dtv * xcv;
            sdt += dtv;
            ull w2 = pack2(w, w);
            if (fast) {
                float p  = __expf(dtv * a0);
                float p2 = p * p;
                ull pk2 = pack2(p, p2);
                ull pp2 = pack2(p2, p2);
                #pragma unroll
                for (int k = 0; k < 8; k++) {
                    h2[k] = fma2(h2[k], pk2, mul2(w2, bb2[k]));
                    pk2 = mul2(pk2, pp2);
                }
            } else {
                #pragma unroll
                for (int k = 0; k < 8; k++) {
                    ull dA2 = pack2(__expf(dtv * a[2*k]), __expf(dtv * a[2*k+1]));
                    h2[k] = fma2(h2[k], dA2, mul2(w2, bb2[k]));
                }
            }
        }
    }

    size_t o = (((size_t)n*NCHUNK + ch)*DD + e) * NST;
    #pragma unroll
    for (int q = 0; q < 4; q++) {
        float x0, y0, x1, y1;
        unpack2(h2[2*q+0], x0, y0);
        unpack2(h2[2*q+1], x1, y1);
        ((float4*)&g_he[o])[q] = make_float4(x0, y0, x1, y1);
        ((float4*)&g_P[o])[q] = make_float4(__expf(a[4*q]*sdt),   __expf(a[4*q+1]*sdt),
                                            __expf(a[4*q+2]*sdt), __expf(a[4*q+3]*sdt));
    }
}

// ---------------- carry ----------------
__global__ void k_carry()
{
    int idx = blockIdx.x * 256 + threadIdx.x;
    int e = idx & (DD - 1);
    int n = idx >> 9;

    float hc[NST];
    #pragma unroll
    for (int s = 0; s < NST; s++) hc[s] = 0.f;

    for (int ch = 0; ch < NCHUNK; ch++) {
        size_t o = (((size_t)n*NCHUNK + ch)*DD + e) * NST;
        #pragma unroll
        for (int q = 0; q < 4; q++)
            ((float4*)&g_h0[o])[q] = make_float4(hc[4*q], hc[4*q+1], hc[4*q+2], hc[4*q+3]);
        #pragma unroll
        for (int q = 0; q < 4; q++) {
            float4 P = ((const float4*)&g_P[o])[q];
            float4 E = ((const float4*)&g_he[o])[q];
            hc[4*q+0] = fmaf(P.x, hc[4*q+0], E.x);
            hc[4*q+1] = fmaf(P.y, hc[4*q+1], E.y);
            hc[4*q+2] = fmaf(P.z, hc[4*q+2], E.z);
            hc[4*q+3] = fmaf(P.w, hc[4*q+3], E.w);
        }
    }
}

// ---------------- scan pass 2: consumes stored dt, no dv load ----------------
__global__ void k_scan2(const float* __restrict__ Alog, const float* __restrict__ Dp)
{
    __shared__ float sdbc[SUB * 32];   // cols 16..47: [B | C]
    int n  = blockIdx.z;
    int ch = blockIdx.y;
    int e  = blockIdx.x * 128 + threadIdx.x;

    float a[NST];
    #pragma unroll
    for (int s = 0; s < NST; s++) a[s] = -__expf(Alog[e*NST + s]);
    float a0 = a[0];
    bool fast = (a0 < 0.f);
    #pragma unroll
    for (int s = 0; s < NST; s++)
        fast = fast && (fabsf(a[s]/a0 - (float)(s+1)) < 1e-3f);

    float De = Dp[e];

    ull h2[8];
    size_t o = (((size_t)n*NCHUNK + ch)*DD + e) * NST;
    #pragma unroll
    for (int q = 0; q < 4; q++) {
        float4 t = ((const float4*)&g_h0[o])[q];
        h2[2*q+0] = pack2(t.x, t.y);
        h2[2*q+1] = pack2(t.z, t.w);
    }

    int l0 = ch * CH;
    for (int sl = 0; sl < CH; sl += SUB) {
        __syncthreads();
        const float* gsrc = &g_dbc[((size_t)n*LL + l0 + sl) * 48] + 16;
        for (int idx = threadIdx.x; idx < SUB*32; idx += 128) {
            int r = idx >> 5, cI = idx & 31;
            sdbc[idx] = gsrc[r*48 + cI];
        }
        __syncthreads();

        for (int r = 0; r < SUB; r++) {
            size_t row = (size_t)n*LL + l0 + sl + r;
            const float* dr = &sdbc[r * 32];
            ull bb2[8], cc2[8];
            #pragma unroll
            for (int q = 0; q < 4; q++) {
                float4 t1 = ((const float4*)dr)[q];
                bb2[2*q+0] = pack2(t1.x, t1.y); bb2[2*q+1] = pack2(t1.z, t1.w);
                float4 t2 = ((const float4*)dr)[4+q];
                cc2[2*q+0] = pack2(t2.x, t2.y); cc2[2*q+1] = pack2(t2.z, t2.w);
            }
            float dtv = g_dtf[row*DD + e];
            float xcv = __bfloat162float(g_xcb[row*DD + e]);
            float zv  = __bfloat162float(g_z[row*DD + e]);
            float w  = dtv * xcv;
            ull w2 = pack2(w, w);
            ull yv2 = pack2(0.f, 0.f);
            if (fast) {
                float p  = __expf(dtv * a0);
                float p2 = p * p;
                ull pk2 = pack2(p, p2);
                ull pp2 = pack2(p2, p2);
                #pragma unroll
                for (int k = 0; k < 8; k++) {
                    h2[k] = fma2(h2[k], pk2, mul2(w2, bb2[k]));
                    yv2   = fma2(h2[k], cc2[k], yv2);
                    pk2   = mul2(pk2, pp2);
                }
            } else {
                #pragma unroll
                for (int k = 0; k < 8; k++) {
                    ull dA2 = pack2(__expf(dtv * a[2*k]), __expf(dtv * a[2*k+1]));
                    h2[k] = fma2(h2[k], dA2, mul2(w2, bb2[k]));
                    yv2   = fma2(h2[k], cc2[k], yv2);
                }
            }
            float ylo, yhi; unpack2(yv2, ylo, yhi);
            float yv = ylo + yhi;
            yv = (yv + xcv*De) * (zv / (1.f + __expf(-zv)));
            g_ybf[row*DD + e] = __float2bfloat16(yv);
        }
    }
}

// ---------------- merge + residual ----------------
__global__ void k_final(const float* __restrict__ d0, const float* __restrict__ d1,
                        float* __restrict__ out)
{
    int idx = blockIdx.x * 256 + threadIdx.x;
    int w = idx % 96;
    int t = idx / 96;
    int h = t % 96; t /= 96;
    int c = t % 256; t /= 256;
    int b = t & 3;
    int d = t >> 2;

    int k, l;
    if ((h & 1) == 0) {
        if ((w & 1) == 0) { k = 0; l = (h>>1)*96 + (w>>1) + 48*d; }
        else              { k = 2; l = (LL-1) - ((h>>1)*96 + (w>>1) + 48*d); }
    } else {
        if ((w & 1) == 1) { k = 1; l = (w>>1)*96 + (h>>1) + 48*d; }
        else              { k = 3; l = (LL-1) - ((w>>1)*96 + (h>>1) + 48*d); }
    }
    int n = b*4 + k;
    const float* dsc = d ? d1 : d0;
    int local = idx - d * (NB*CC*HW);

    out[idx] = 2.f*dsc[local] + __bfloat162float(g_outTb[(size_t)c * MM + (size_t)n*LL + l]);
}

// ---------------- host launch ----------------
extern "C" void kernel_launch(void* const* d_in, const int* in_sizes, int n_in,
                              void* d_out, int out_size)
{
    const float* desc0 = (const float*)d_in[0];
    const float* desc1 = (const float*)d_in[1];
    const float* nw    = (const float*)d_in[2];
    const float* nbi   = (const float*)d_in[3];
    const float* inw   = (const float*)d_in[4];
    const float* cw    = (const float*)d_in[5];
    const float* cb    = (const float*)d_in[6];
    const float* xpw   = (const float*)d_in[7];
    const float* dtw   = (const float*)d_in[8];
    const float* dtb   = (const float*)d_in[9];
    const float* alog  = (const float*)d_in[10];
    const float* dpar  = (const float*)d_in[11];
    const float* opw   = (const float*)d_in[12];

    __nv_bfloat16 *p_xg, *p_ybf, *p_wib, *p_wob, *p_xi, *p_z, *p_outTb;
    cudaGetSymbolAddress((void**)&p_xg,  g_xg);
    cudaGetSymbolAddress((void**)&p_xi,  g_xi);
    cudaGetSymbolAddress((void**)&p_z,   g_z);
    cudaGetSymbolAddress((void**)&p_ybf, g_ybf);
    cudaGetSymbolAddress((void**)&p_outTb, g_outTb);
    cudaGetSymbolAddress((void**)&p_wib, g_wib);
    cudaGetSymbolAddress((void**)&p_wob, g_wob);

    // 0. fused weight prep + gather-transpose
    k_pt<<<1344 + 18432, 256>>>(inw, opw, xpw, nw, nbi, desc0, desc1);
    // 1. LN stats
    k_stats<<<MM/8, 256>>>();
    // 2. in_proj GEMM (LN folded)
    hgemm128<1><<<dim3(1024/128, MM/128), 256>>>(p_xg, p_wib, p_xi, p_z, 256);
    // 3. conv+silu fused x_proj  <-- profiled slot
    k_xproj<<<dim3(MM/128), 256>>>(cw, cb);
    // 4. chunked scan (scan1 stores dt; scan2 reuses)
    k_scan1<<<dim3(DD/128, NCHUNK, NSEQ), 128>>>(alog, dtw, dtb);
    k_carry<<<NSEQ*DD/256, 256>>>();
    k_scan2<<<dim3(DD/128, NCHUNK, NSEQ), 128>>>(alog, dpar);
    // 5. out_proj -> bf16 transposed
    hgemm128<2><<<dim3(256/128, MM/128), 256>>>(p_ybf, p_wob, p_outTb, nullptr, 512);
    // 6. merge + residual
    k_final<<<dim3(out_size/256), 256>>>(desc0, desc1, (float*)d_out);
}

// round 16
// speedup vs baseline: 1.1231x; 1.1231x over previous
#include <cuda_runtime.h>
#include <cuda_bf16.h>
#include <cstdint>
#include <math.h>

// Problem constants
#define NB    4
#define NSEQ  16
#define LL    4608
#define CC    256
#define DD    512
#define MM    73728
#define HH    96
#define WW    96
#define HW    9216
#define RNK   16
#define NST   16
#define NCHUNK 16
#define CH    288      // LL / NCHUNK
#define SUB   72       // dbc smem slab rows (CH/SUB = 4)

// ---------------- scratch (device globals) ----------------
__device__ __align__(16) __nv_bfloat16 g_xg [(size_t)MM * CC];   // gathered x (n,l,c) bf16
__device__ __align__(16) float g_mu[MM];                         // LN mean per row
__device__ __align__(16) float g_rs[MM];                         // LN rstd per row
__device__ __align__(16) float g_u1[1024];                       // W @ nw
__device__ __align__(16) float g_u2[1024];                       // W @ nb
__device__ __align__(16) __nv_bfloat16 g_xi [(size_t)MM * DD];   // in_proj xi half bf16
__device__ __align__(16) __nv_bfloat16 g_z  [(size_t)MM * DD];   // in_proj z half bf16
__device__ __align__(16) __nv_bfloat16 g_xcb[(size_t)MM * DD];   // conv+silu bf16
__device__ __align__(16) float g_dbc[(size_t)MM * 48];           // x_proj out compact: [dt_in|B|C]
__device__ __align__(16) __nv_bfloat16 g_ybf[(size_t)MM * DD];   // y bf16
__device__ __align__(16) __nv_bfloat16 g_outTb[(size_t)CC * MM]; // out_proj result, c-major bf16
__device__ __align__(16) __nv_bfloat16 g_wib[1024 * 256];        // (in_proj_w * nw) bf16
__device__ __align__(16) __nv_bfloat16 g_wob[256 * 512];         // out_proj_w bf16
__device__ __align__(16) __nv_bfloat16 g_wxb[64 * 512];          // x_proj_w bf16 padded 48->64
__device__ __align__(16) float g_P [(size_t)NSEQ * NCHUNK * DD * NST];
__device__ __align__(16) float g_he[(size_t)NSEQ * NCHUNK * DD * NST];
__device__ __align__(16) float g_h0[(size_t)NSEQ * NCHUNK * DD * NST];

// ---------------- K_prep: all weight conversions + u1/u2 (one launch) ----------------
__global__ void k_prep(const float* __restrict__ inw, const float* __restrict__ opw,
                       const float* __restrict__ xpw, const float* __restrict__ nw,
                       const float* __restrict__ nb)
{
    int bid = blockIdx.x;
    int c = threadIdx.x;
    if (bid < 1024) {
        int e = bid;
        float wv = inw[e*256 + c];
        float nwc = nw[c];
        g_wib[e*256 + c] = __float2bfloat16(wv * nwc);
        float s1 = wv * nwc, s2 = wv * nb[c];
        #pragma unroll
        for (int o = 16; o > 0; o >>= 1) {
            s1 += __shfl_xor_sync(0xffffffffu, s1, o);
            s2 += __shfl_xor_sync(0xffffffffu, s2, o);
        }
        __shared__ float a1[8], a2[8];
        int wid = c >> 5;
        if ((c & 31) == 0) { a1[wid] = s1; a2[wid] = s2; }
        __syncthreads();
        if (c == 0) {
            float t1 = 0.f, t2 = 0.f;
            #pragma unroll
            for (int q = 0; q < 8; q++) { t1 += a1[q]; t2 += a2[q]; }
            g_u1[e] = t1; g_u2[e] = t2;
        }
    } else if (bid < 1280) {
        int r = bid - 1024;
        g_wob[r*512 + c]       = __float2bfloat16(opw[r*512 + c]);
        g_wob[r*512 + c + 256] = __float2bfloat16(opw[r*512 + c + 256]);
    } else {
        int r = bid - 1280;
        float v0 = (r < 48) ? xpw[r*512 + c]       : 0.f;
        float v1 = (r < 48) ? xpw[r*512 + c + 256] : 0.f;
        g_wxb[r*512 + c]       = __float2bfloat16(v0);
        g_wxb[r*512 + c + 256] = __float2bfloat16(v1);
    }
}

// ---------------- K_trans: gather-transpose desc -> g_xg (n,l,c) bf16 ----------------
__global__ void k_trans(const float* __restrict__ d0, const float* __restrict__ d1)
{
    __shared__ float tile[32][33];
    int h  = blockIdx.x;
    int wt = blockIdx.y % 3, ct = blockIdx.y / 3;
    int bd = blockIdx.z;
    int b = bd >> 1, d = bd & 1;
    int w0 = wt * 32, c0 = ct * 32;
    int tx = threadIdx.x, ty = threadIdx.y;

    const float* src = d ? d1 : d0;
    #pragma unroll
    for (int s = 0; s < 4; s++) {
        int cl = ty + s * 8;
        tile[cl][tx] = src[((size_t)(b*CC + c0 + cl)*HH + h)*WW + w0 + tx];
    }
    __syncthreads();

    #pragma unroll
    for (int s = 0; s < 4; s++) {
        int wl = ty + s * 8;
        int w  = w0 + wl;
        float v = tile[tx][wl];
        int k, l;
        if ((h & 1) == 0) {
            if ((w & 1) == 0) { k = 0; l = (h>>1)*96 + (w>>1) + 48*d; }
            else              { k = 2; l = (LL-1) - ((h>>1)*96 + (w>>1) + 48*d); }
        } else {
            if ((w & 1) == 1) { k = 1; l = (w>>1)*96 + (h>>1) + 48*d; }
            else              { k = 3; l = (LL-1) - ((w>>1)*96 + (h>>1) + 48*d); }
        }
        int n = b*4 + k;
        g_xg[((size_t)n*LL + l)*CC + c0 + tx] = __float2bfloat16(v);
    }
}

// ---------------- K_stats: per-row LN stats ----------------
__global__ void k_stats()
{
    int row = blockIdx.x * 8 + (threadIdx.x >> 5);
    int lane = threadIdx.x & 31;
    const __nv_bfloat16* p = &g_xg[(size_t)row * CC];

    uint4 u = *(const uint4*)&p[lane * 8];
    const __nv_bfloat162* h2 = (const __nv_bfloat162*)&u;
    float s1 = 0.f, s2 = 0.f;
    #pragma unroll
    for (int q = 0; q < 4; q++) {
        float2 f = __bfloat1622float2(h2[q]);
        s1 += f.x + f.y;
        s2 += f.x*f.x + f.y*f.y;
    }
    #pragma unroll
    for (int o = 16; o > 0; o >>= 1) {
        s1 += __shfl_xor_sync(0xffffffffu, s1, o);
        s2 += __shfl_xor_sync(0xffffffffu, s2, o);
    }
    if (lane == 0) {
        float mean = s1 * (1.f/256.f);
        float var  = s2 * (1.f/256.f) - mean*mean;
        g_mu[row] = mean;
        g_rs[row] = rsqrtf(var + 1e-5f);
    }
}

// ---------------- mma helpers ----------------
__device__ __forceinline__ unsigned int smem_u32(const void* p) {
    return (unsigned int)__cvta_generic_to_shared(p);
}
__device__ __forceinline__ void ldsm4(unsigned int* r, unsigned int addr) {
    asm volatile("ldmatrix.sync.aligned.m8n8.x4.shared.b16 {%0,%1,%2,%3}, [%4];"
                 : "=r"(r[0]), "=r"(r[1]), "=r"(r[2]), "=r"(r[3]) : "r"(addr));
}
__device__ __forceinline__ void mma16816(float* c, const unsigned int* a,
                                         unsigned int b0, unsigned int b1) {
    asm volatile("mma.sync.aligned.m16n8k16.row.col.f32.bf16.bf16.f32 "
                 "{%0,%1,%2,%3},{%4,%5,%6,%7},{%8,%9},{%0,%1,%2,%3};"
                 : "+f"(c[0]), "+f"(c[1]), "+f"(c[2]), "+f"(c[3])
                 : "r"(a[0]), "r"(a[1]), "r"(a[2]), "r"(a[3]), "r"(b0), "r"(b1));
}
__device__ __forceinline__ void cpa16(unsigned int d, const void* s) {
    asm volatile("cp.async.cg.shared.global [%0], [%1], 16;" :: "r"(d), "l"(s));
}
__device__ __forceinline__ void cp_commit() { asm volatile("cp.async.commit_group;"); }
template<int N> __device__ __forceinline__ void cp_wait() {
    asm volatile("cp.async.wait_group %0;" :: "n"(N));
}

// ---------------- hgemm 128x128x32, 2-stage cp.async (R7/R10 proven) ----------------
template<int MODE>
__global__ __launch_bounds__(256) void hgemm128(
    const __nv_bfloat16* __restrict__ A, const __nv_bfloat16* __restrict__ B,
    __nv_bfloat16* __restrict__ O1, __nv_bfloat16* __restrict__ O2,
    int Kd)
{
    const int LDS = 40;
    __shared__ __nv_bfloat16 As[2][128 * LDS];
    __shared__ __nv_bfloat16 Bs[2][128 * LDS];

    int tid  = threadIdx.x;
    int wid  = tid >> 5, lane = tid & 31;
    int wm   = (wid & 1) * 64;
    int wn   = (wid >> 1) * 32;
    int m0   = blockIdx.y * 128;
    int n0   = blockIdx.x * 128;

    float c[4][4][4];
    #pragma unroll
    for (int i = 0; i < 4; i++)
        #pragma unroll
        for (int j = 0; j < 4; j++)
            #pragma unroll
            for (int q = 0; q < 4; q++) c[i][j][q] = 0.f;

    int ar = tid >> 2;
    int ac = (tid & 3) * 8;
    int NK = Kd >> 5;

    {
        cpa16(smem_u32(&As[0][ar*LDS + ac]),        &A[(size_t)(m0 + ar)      * Kd + ac]);
        cpa16(smem_u32(&As[0][(ar+64)*LDS + ac]),   &A[(size_t)(m0 + ar + 64) * Kd + ac]);
        cpa16(smem_u32(&Bs[0][ar*LDS + ac]),        &B[(size_t)(n0 + ar)      * Kd + ac]);
        cpa16(smem_u32(&Bs[0][(ar+64)*LDS + ac]),   &B[(size_t)(n0 + ar + 64) * Kd + ac]);
        cp_commit();
    }

    for (int it = 0; it < NK; it++) {
        if (it + 1 < NK) {
            int st = (it + 1) & 1, k0 = (it + 1) * 32;
            cpa16(smem_u32(&As[st][ar*LDS + ac]),      &A[(size_t)(m0 + ar)      * Kd + k0 + ac]);
            cpa16(smem_u32(&As[st][(ar+64)*LDS + ac]), &A[(size_t)(m0 + ar + 64) * Kd + k0 + ac]);
            cpa16(smem_u32(&Bs[st][ar*LDS + ac]),      &B[(size_t)(n0 + ar)      * Kd + k0 + ac]);
            cpa16(smem_u32(&Bs[st][(ar+64)*LDS + ac]), &B[(size_t)(n0 + ar + 64) * Kd + k0 + ac]);
            cp_commit();
            cp_wait<1>();
        } else {
            cp_wait<0>();
        }
        __syncthreads();

        int cur = it & 1;
        #pragma unroll
        for (int ks = 0; ks < 2; ks++) {
            int kk = ks * 16;
            unsigned int a[4][4], b[2][4];
            #pragma unroll
            for (int i = 0; i < 4; i++)
                ldsm4(a[i], smem_u32(&As[cur][(wm + i*16 + (lane & 15)) * LDS + kk + ((lane >> 4) * 8)]));
            #pragma unroll
            for (int j2 = 0; j2 < 2; j2++)
                ldsm4(b[j2], smem_u32(&Bs[cur][(wn + j2*16 + (lane & 15)) * LDS + kk + ((lane >> 4) * 8)]));
            #pragma unroll
            for (int i = 0; i < 4; i++)
                #pragma unroll
                for (int j2 = 0; j2 < 2; j2++) {
                    mma16816(c[i][2*j2+0], a[i], b[j2][0], b[j2][2]);
                    mma16816(c[i][2*j2+1], a[i], b[j2][1], b[j2][3]);
                }
        }
        __syncthreads();
    }

    int g = lane >> 2, t4 = lane & 3;
    #pragma unroll
    for (int i = 0; i < 4; i++) {
        int r0 = m0 + wm + i*16 + g;
        int r1 = r0 + 8;
        float f0 = 0.f, g0 = 0.f, f1 = 0.f, g1 = 0.f;
        if (MODE == 1) {
            f0 = g_rs[r0]; g0 = -f0 * g_mu[r0];
            f1 = g_rs[r1]; g1 = -f1 * g_mu[r1];
        }
        #pragma unroll
        for (int j = 0; j < 4; j++) {
            int col = n0 + wn + j*8 + t4*2;
            if (MODE == 1) {
                float U10 = g_u1[col], U11 = g_u1[col+1];
                float U20 = g_u2[col], U21 = g_u2[col+1];
                float v00 = c[i][j][0]*f0 + g0*U10 + U20;
                float v01 = c[i][j][1]*f0 + g0*U11 + U21;
                float v10 = c[i][j][2]*f1 + g1*U10 + U20;
                float v11 = c[i][j][3]*f1 + g1*U11 + U21;
                __nv_bfloat162 a01 = __floats2bfloat162_rn(v00, v01);
                __nv_bfloat162 a23 = __floats2bfloat162_rn(v10, v11);
                if (col < 512) {
                    *(__nv_bfloat162*)&O1[(size_t)r0 * 512 + col] = a01;
                    *(__nv_bfloat162*)&O1[(size_t)r1 * 512 + col] = a23;
                } else {
                    *(__nv_bfloat162*)&O2[(size_t)r0 * 512 + col - 512] = a01;
                    *(__nv_bfloat162*)&O2[(size_t)r1 * 512 + col - 512] = a23;
                }
            } else {
                O1[(size_t)col * MM + r0]     = __float2bfloat16(c[i][j][0]);
                O1[(size_t)(col+1) * MM + r0] = __float2bfloat16(c[i][j][1]);
                O1[(size_t)col * MM + r1]     = __float2bfloat16(c[i][j][2]);
                O1[(size_t)(col+1) * MM + r1] = __float2bfloat16(c[i][j][3]);
            }
        }
    }
}

// ---------------- x_proj GEMM, BM=64 tile (double grid, half serial build) ----------------
// 256 threads: warps 2(M,32rows) x 4(N,16cols). One 64-row A-build pass per k-iter.
__global__ __launch_bounds__(256) void k_xproj(const float* __restrict__ cw, const float* __restrict__ cb)
{
    const int LDS = 40;
    __shared__ __nv_bfloat16 As[64 * LDS];
    __shared__ __nv_bfloat16 Bs[64 * LDS];
    __shared__ float scw[512*4];
    __shared__ float scb[512];

    int tid = threadIdx.x;
    int wid = tid >> 5, lane = tid & 31;
    int wm  = (wid & 1) * 32;        // 2 warps in M
    int wn  = (wid >> 1) * 16;       // 4 warps in N
    int m0  = blockIdx.x * 64;

    for (int i = tid; i < 2048; i += 256) scw[i] = cw[i];
    for (int i = tid; i < 512;  i += 256) scb[i] = cb[i];

    float c[2][2][4];
    #pragma unroll
    for (int i = 0; i < 2; i++)
        #pragma unroll
        for (int j = 0; j < 2; j++)
            #pragma unroll
            for (int q = 0; q < 4; q++) c[i][j][q] = 0.f;

    int R  = tid >> 2;               // 0..63
    int k8 = (tid & 3) * 8;
    int lr = (m0 + R) % LL;          // 64 | LL so rows stay in-sequence
    int m  = m0 + R;
    __syncthreads();

    for (int k0 = 0; k0 < 512; k0 += 32) {
        // build A row R, cols k0+k8..+8 : conv(width4) + silu, also write g_xcb
        {
            float acc[8];
            #pragma unroll
            for (int q = 0; q < 8; q++) acc[q] = scb[k0 + k8 + q];
            #pragma unroll
            for (int t = 0; t < 4; t++) {
                if (lr - 3 + t >= 0) {
                    uint4 u = *(const uint4*)&g_xi[(size_t)(m - 3 + t)*512 + k0 + k8];
                    __nv_bfloat162* p = (__nv_bfloat162*)&u;
                    #pragma unroll
                    for (int q2 = 0; q2 < 4; q2++) {
                        float2 f = __bfloat1622float2(p[q2]);
                        acc[2*q2+0] = fmaf(f.x, scw[(k0+k8+2*q2+0)*4 + t], acc[2*q2+0]);
                        acc[2*q2+1] = fmaf(f.y, scw[(k0+k8+2*q2+1)*4 + t], acc[2*q2+1]);
                    }
                }
            }
            uint4 o;
            __nv_bfloat162* q = (__nv_bfloat162*)&o;
            #pragma unroll
            for (int q2 = 0; q2 < 4; q2++) {
                float v0 = acc[2*q2+0], v1 = acc[2*q2+1];
                v0 = v0 / (1.f + __expf(-v0));
                v1 = v1 / (1.f + __expf(-v1));
                q[q2] = __floats2bfloat162_rn(v0, v1);
            }
            *(uint4*)&As[R * LDS + k8] = o;
            *(uint4*)&g_xcb[(size_t)m * 512 + k0 + k8] = o;
        }
        // B: 64 rows x 32 cols
        *(uint4*)&Bs[R * LDS + k8] = *(const uint4*)&g_wxb[(size_t)R * 512 + k0 + k8];
        __syncthreads();

        #pragma unroll
        for (int ks = 0; ks < 2; ks++) {
            int kk = ks * 16;
            unsigned int a[2][4], b[4];
            #pragma unroll
            for (int i = 0; i < 2; i++)
                ldsm4(a[i], smem_u32(&As[(wm + i*16 + (lane & 15)) * LDS + kk + ((lane >> 4) * 8)]));
            ldsm4(b, smem_u32(&Bs[(wn + (lane & 15)) * LDS + kk + ((lane >> 4) * 8)]));
            #pragma unroll
            for (int i = 0; i < 2; i++) {
                mma16816(c[i][0], a[i], b[0], b[2]);
                mma16816(c[i][1], a[i], b[1], b[3]);
            }
        }
        __syncthreads();
    }

    int g = lane >> 2, t4 = lane & 3;
    #pragma unroll
    for (int i = 0; i < 2; i++)
        #pragma unroll
        for (int j = 0; j < 2; j++) {
            int row = m0 + wm + i*16 + g;
            int col = wn + j*8 + t4*2;
            if (col < 48) {
                *(float2*)&g_dbc[(size_t)row * 48 + col]       = make_float2(c[i][j][0], c[i][j][1]);
                *(float2*)&g_dbc[(size_t)(row + 8) * 48 + col] = make_float2(c[i][j][2], c[i][j][3]);
            }
        }
}

// ---------------- scan helpers ----------------
__device__ __forceinline__ float inline_dt(const float* __restrict__ dr, const float* dtwr, float dtbv)
{
    float v = dtbv;
    #pragma unroll
    for (int r = 0; r < RNK; r++) v = fmaf(dr[r], dtwr[r], v);
    return (v > 15.f) ? v : __logf(1.f + __expf(v));
}

// ---------------- scan pass 1 ----------------
__global__ void k_scan1(const float* __restrict__ Alog,
                        const float* __restrict__ dtw, const float* __restrict__ dtb)
{
    __shared__ float sdbc[SUB * 48];
    int n  = blockIdx.z;
    int ch = blockIdx.y;
    int e  = blockIdx.x * 128 + threadIdx.x;

    float a[NST];
    #pragma unroll
    for (int s = 0; s < NST; s++) a[s] = -__expf(Alog[e*NST + s]);
    float a0 = a[0];
    bool fast = (a0 < 0.f);
    #pragma unroll
    for (int s = 0; s < NST; s++)
        fast = fast && (fabsf(a[s]/a0 - (float)(s+1)) < 1e-3f);

    float dtwr[RNK];
    #pragma unroll
    for (int r = 0; r < RNK; r++) dtwr[r] = dtw[e*RNK + r];
    float dtbv = dtb[e];

    float h[NST];
    #pragma unroll
    for (int s = 0; s < NST; s++) h[s] = 0.f;
    float sdt = 0.f;
    int l0 = ch * CH;

    for (int sl = 0; sl < CH; sl += SUB) {
        __syncthreads();
        const float* gsrc = &g_dbc[((size_t)n*LL + l0 + sl) * 48];
        for (int idx = threadIdx.x; idx < SUB*48; idx += 128)
            sdbc[idx] = gsrc[idx];
        __syncthreads();

        for (int r = 0; r < SUB; r++) {
            size_t row = (size_t)n*LL + l0 + sl + r;
            const float* dr = &sdbc[r * 48];
            float dv[RNK], bb[NST];
            #pragma unroll
            for (int q = 0; q < 4; q++) {
                float4 t0 = ((const float4*)dr)[q];
                dv[4*q]=t0.x; dv[4*q+1]=t0.y; dv[4*q+2]=t0.z; dv[4*q+3]=t0.w;
                float4 t1 = ((const float4*)dr)[4+q];
                bb[4*q]=t1.x; bb[4*q+1]=t1.y; bb[4*q+2]=t1.z; bb[4*q+3]=t1.w;
            }
            float dtv = inline_dt(dv, dtwr, dtbv);
            float xcv = __bfloat162float(g_xcb[row*DD + e]);
            float w = dtv * xcv;
            sdt += dtv;
            if (fast) {
                float p  = __expf(dtv * a0);
                float pk = p;
                #pragma unroll
                for (int s = 0; s < NST; s++) { h[s] = fmaf(h[s], pk, w * bb[s]); pk *= p; }
            } else {
                #pragma unroll
                for (int s = 0; s < NST; s++) {
                    float dA = __expf(dtv * a[s]);
                    h[s] = fmaf(h[s], dA, w * bb[s]);
                }
            }
        }
    }

    size_t o = (((size_t)n*NCHUNK + ch)*DD + e) * NST;
    #pragma unroll
    for (int q = 0; q < 4; q++) {
        ((float4*)&g_he[o])[q] = make_float4(h[4*q], h[4*q+1], h[4*q+2], h[4*q+3]);
        ((float4*)&g_P[o])[q] = make_float4(__expf(a[4*q]*sdt),   __expf(a[4*q+1]*sdt),
                                            __expf(a[4*q+2]*sdt), __expf(a[4*q+3]*sdt));
    }
}

// ---------------- carry ----------------
__global__ void k_carry()
{
    int idx = blockIdx.x * 256 + threadIdx.x;
    int e = idx & (DD - 1);
    int n = idx >> 9;

    float hc[NST];
    #pragma unroll
    for (int s = 0; s < NST; s++) hc[s] = 0.f;

    for (int ch = 0; ch < NCHUNK; ch++) {
        size_t o = (((size_t)n*NCHUNK + ch)*DD + e) * NST;
        #pragma unroll
        for (int q = 0; q < 4; q++)
            ((float4*)&g_h0[o])[q] = make_float4(hc[4*q], hc[4*q+1], hc[4*q+2], hc[4*q+3]);
        #pragma unroll
        for (int q = 0; q < 4; q++) {
            float4 P = ((const float4*)&g_P[o])[q];
            float4 E = ((const float4*)&g_he[o])[q];
            hc[4*q+0] = fmaf(P.x, hc[4*q+0], E.x);
            hc[4*q+1] = fmaf(P.y, hc[4*q+1], E.y);
            hc[4*q+2] = fmaf(P.z, hc[4*q+2], E.z);
            hc[4*q+3] = fmaf(P.w, hc[4*q+3], E.w);
        }
    }
}

// ---------------- scan pass 2 ----------------
__global__ void k_scan2(const float* __restrict__ Alog, const float* __restrict__ Dp,
                        const float* __restrict__ dtw, const float* __restrict__ dtb)
{
    __shared__ float sdbc[SUB * 48];
    int n  = blockIdx.z;
    int ch = blockIdx.y;
    int e  = blockIdx.x * 128 + threadIdx.x;

    float a[NST];
    #pragma unroll
    for (int s = 0; s < NST; s++) a[s] = -__expf(Alog[e*NST + s]);
    float a0 = a[0];
    bool fast = (a0 < 0.f);
    #pragma unroll
    for (int s = 0; s < NST; s++)
        fast = fast && (fabsf(a[s]/a0 - (float)(s+1)) < 1e-3f);

    float dtwr[RNK];
    #pragma unroll
    for (int r = 0; r < RNK; r++) dtwr[r] = dtw[e*RNK + r];
    float dtbv = dtb[e];
    float De = Dp[e];

    float h[NST];
    size_t o = (((size_t)n*NCHUNK + ch)*DD + e) * NST;
    #pragma unroll
    for (int q = 0; q < 4; q++) {
        float4 t = ((const float4*)&g_h0[o])[q];
        h[4*q] = t.x; h[4*q+1] = t.y; h[4*q+2] = t.z; h[4*q+3] = t.w;
    }

    int l0 = ch * CH;
    for (int sl = 0; sl < CH; sl += SUB) {
        __syncthreads();
        const float* gsrc = &g_dbc[((size_t)n*LL + l0 + sl) * 48];
        for (int idx = threadIdx.x; idx < SUB*48; idx += 128)
            sdbc[idx] = gsrc[idx];
        __syncthreads();

        for (int r = 0; r < SUB; r++) {
            size_t row = (size_t)n*LL + l0 + sl + r;
            const float* dr = &sdbc[r * 48];
            float dv[RNK], bb[NST], cc[NST];
            #pragma unroll
            for (int q = 0; q < 4; q++) {
                float4 t0 = ((const float4*)dr)[q];
                dv[4*q]=t0.x; dv[4*q+1]=t0.y; dv[4*q+2]=t0.z; dv[4*q+3]=t0.w;
                float4 t1 = ((const float4*)dr)[4+q];
                bb[4*q]=t1.x; bb[4*q+1]=t1.y; bb[4*q+2]=t1.z; bb[4*q+3]=t1.w;
                float4 t2 = ((const float4*)dr)[8+q];
                cc[4*q]=t2.x; cc[4*q+1]=t2.y; cc[4*q+2]=t2.z; cc[4*q+3]=t2.w;
            }
            float dtv = inline_dt(dv, dtwr, dtbv);
            float xcv = __bfloat162float(g_xcb[row*DD + e]);
            float zv  = __bfloat162float(g_z[row*DD + e]);
            float w  = dtv * xcv;
            float yv = 0.f;
            if (fast) {
                float p  = __expf(dtv * a0);
                float pk = p;
                #pragma unroll
                for (int s = 0; s < NST; s++) {
                    h[s] = fmaf(h[s], pk, w * bb[s]);
                    yv   = fmaf(h[s], cc[s], yv);
                    pk  *= p;
                }
            } else {
                #pragma unroll
                for (int s = 0; s < NST; s++) {
                    float dA = __expf(dtv * a[s]);
                    h[s] = fmaf(h[s], dA, w * bb[s]);
                    yv   = fmaf(h[s], cc[s], yv);
                }
            }
            yv = (yv + xcv*De) * (zv / (1.f + __expf(-zv)));
            g_ybf[row*DD + e] = __float2bfloat16(yv);
        }
    }
}

// ---------------- merge + residual ----------------
__global__ void k_final(const float* __restrict__ d0, const float* __restrict__ d1,
                        float* __restrict__ out)
{
    int idx = blockIdx.x * 256 + threadIdx.x;
    int w = idx % 96;
    int t = idx / 96;
    int h = t % 96; t /= 96;
    int c = t % 256; t /= 256;
    int b = t & 3;
    int d = t >> 2;

    int k, l;
    if ((h & 1) == 0) {
        if ((w & 1) == 0) { k = 0; l = (h>>1)*96 + (w>>1) + 48*d; }
        else              { k = 2; l = (LL-1) - ((h>>1)*96 + (w>>1) + 48*d); }
    } else {
        if ((w & 1) == 1) { k = 1; l = (w>>1)*96 + (h>>1) + 48*d; }
        else              { k = 3; l = (LL-1) - ((w>>1)*96 + (h>>1) + 48*d); }
    }
    int n = b*4 + k;
    const float* dsc = d ? d1 : d0;
    int local = idx - d * (NB*CC*HW);

    out[idx] = 2.f*dsc[local] + __bfloat162float(g_outTb[(size_t)c * MM + (size_t)n*LL + l]);
}

// ---------------- host launch ----------------
extern "C" void kernel_launch(void* const* d_in, const int* in_sizes, int n_in,
                              void* d_out, int out_size)
{
    const float* desc0 = (const float*)d_in[0];
    const float* desc1 = (const float*)d_in[1];
    const float* nw    = (const float*)d_in[2];
    const float* nbi   = (const float*)d_in[3];
    const float* inw   = (const float*)d_in[4];
    const float* cw    = (const float*)d_in[5];
    const float* cb    = (const float*)d_in[6];
    const float* xpw   = (const float*)d_in[7];
    const float* dtw   = (const float*)d_in[8];
    const float* dtb   = (const float*)d_in[9];
    const float* alog  = (const float*)d_in[10];
    const float* dpar  = (const float*)d_in[11];
    const float* opw   = (const float*)d_in[12];

    __nv_bfloat16 *p_xg, *p_ybf, *p_wib, *p_wob, *p_xi, *p_z, *p_outTb;
    cudaGetSymbolAddress((void**)&p_xg,  g_xg);
    cudaGetSymbolAddress((void**)&p_xi,  g_xi);
    cudaGetSymbolAddress((void**)&p_z,   g_z);
    cudaGetSymbolAddress((void**)&p_ybf, g_ybf);
    cudaGetSymbolAddress((void**)&p_outTb, g_outTb);
    cudaGetSymbolAddress((void**)&p_wib, g_wib);
    cudaGetSymbolAddress((void**)&p_wob, g_wob);

    // 1. weights + u vectors (fused)
    k_prep<<<1344, 256>>>(inw, opw, xpw, nw, nbi);
    // 2. gather-transpose
    k_trans<<<dim3(96, 24, 8), dim3(32, 8)>>>(desc0, desc1);
    // 3. LN stats
    k_stats<<<MM/8, 256>>>();
    // 4. in_proj GEMM (LN folded)
    hgemm128<1><<<dim3(1024/128, MM/128), 256>>>(p_xg, p_wib, p_xi, p_z, 256);
    // 5. conv+silu fused x_proj (BM=64)
    k_xproj<<<dim3(MM/64), 256>>>(cw, cb);
    // 6. chunked scan
    k_scan1<<<dim3(DD/128, NCHUNK, NSEQ), 128>>>(alog, dtw, dtb);
    k_carry<<<NSEQ*DD/256, 256>>>();
    k_scan2<<<dim3(DD/128, NCHUNK, NSEQ), 128>>>(alog, dpar, dtw, dtb);
    // 7. out_proj -> bf16 transposed
    hgemm128<2><<<dim3(256/128, MM/128), 256>>>(p_ybf, p_wob, p_outTb, nullptr, 512);
    // 8. merge + residual
    k_final<<<dim3(out_size/256), 256>>>(desc0, desc1, (float*)d_out);
}